// round 3
// baseline (speedup 1.0000x reference)
#include <cuda_runtime.h>
#include <cstdint>

#define N_NODES 100000
#define E_EDGES 800000
#define HIDF 128
#define OUTF 40
#define BN_EPS 1e-5f

// ---------------- scratch (no allocations allowed) ----------------
__device__ float g_agg[(size_t)N_NODES * HIDF];   // aggregation buffer
__device__ float g_h0 [(size_t)N_NODES * HIDF];   // layer-0 output / normalized
__device__ float g_h1 [(size_t)N_NODES * HIDF];   // layer-1 output / normalized
__device__ float g_cnt[N_NODES];                  // in-degree (float)
__device__ float g_sums[2 * HIDF];                // BN per-channel sum / sumsq

// ---------------- zero fill (graph-capture-safe) ----------------
__global__ void zero_kernel(float4* __restrict__ p, int n4) {
    int i = blockIdx.x * blockDim.x + threadIdx.x;
    if (i < n4) p[i] = make_float4(0.f, 0.f, 0.f, 0.f);
}

__global__ void zero_small_kernel(float* __restrict__ p, int n) {
    int i = blockIdx.x * blockDim.x + threadIdx.x;
    if (i < n) p[i] = 0.0f;
}

// ---------------- degree ----------------
__global__ void degree_kernel(const int* __restrict__ ei, float* __restrict__ cnt,
                              int E, int N) {
    int e = blockIdx.x * blockDim.x + threadIdx.x;
    if (e >= E) return;
    int d = ei[E + e];
    if ((unsigned)d < (unsigned)N) atomicAdd(&cnt[d], 1.0f);
}

// ---------------- scatter-add of source features into agg[dst] ----------------
// One warp per edge; lane l handles float4 chunk l (32*4 = 128 features).
__global__ void scatter_kernel(const float* __restrict__ feat,
                               const int* __restrict__ ei,
                               float* __restrict__ agg, int E, int N) {
    int idx = blockIdx.x * blockDim.x + threadIdx.x;
    int e = idx >> 5;
    if (e >= E) return;
    int c = (idx & 31) << 2;
    int s = ei[e];
    int d = ei[E + e];
    if ((unsigned)s >= (unsigned)N || (unsigned)d >= (unsigned)N) return;
    float4 v = *reinterpret_cast<const float4*>(feat + (size_t)s * HIDF + c);
    float* p = agg + (size_t)d * HIDF + c;
    asm volatile("red.global.add.v4.f32 [%0], {%1,%2,%3,%4};"
                 :: "l"(p), "f"(v.x), "f"(v.y), "f"(v.z), "f"(v.w) : "memory");
}

// ---------------- fused mean + dual GEMM: out = (agg/cnt)@Wl + feat@Wr (+bias) ----
// Block: 128 threads = 4 row-groups x 32 lanes. 32 rows per block.
template <int NC>
__global__ void gemm_kernel(const float* __restrict__ agg,
                            const float* __restrict__ cnt,
                            const float* __restrict__ feat,
                            const float* __restrict__ Wl,
                            const float* __restrict__ Wr,
                            const float* __restrict__ bias,
                            float* __restrict__ out, int nrows) {
    constexpr int CPT = (NC + 31) / 32;
    __shared__ float sm[32][HIDF];
    __shared__ float sx[32][HIDF];
    __shared__ float sinv[32];

    int tid  = threadIdx.x;
    int row0 = blockIdx.x * 32;

    if (tid < 32) {
        int r = row0 + tid;
        float c = (r < nrows) ? cnt[r] : 1.0f;
        sinv[tid] = 1.0f / fmaxf(c, 1.0f);
    }
    __syncthreads();

    // stage 32x128 of scaled agg and feat (coalesced float4 loads)
    #pragma unroll
    for (int i = 0; i < 8; i++) {
        int idx4 = i * 128 + tid;          // [0,1024)
        int r    = idx4 >> 5;              // 32 float4 per row
        int c4   = idx4 & 31;
        int row  = row0 + r;
        float4 a = make_float4(0.f, 0.f, 0.f, 0.f);
        float4 b = make_float4(0.f, 0.f, 0.f, 0.f);
        if (row < nrows) {
            a = reinterpret_cast<const float4*>(agg  + (size_t)row * HIDF)[c4];
            b = reinterpret_cast<const float4*>(feat + (size_t)row * HIDF)[c4];
        }
        float iv = sinv[r];
        a.x *= iv; a.y *= iv; a.z *= iv; a.w *= iv;
        reinterpret_cast<float4*>(&sm[r][0])[c4] = a;
        reinterpret_cast<float4*>(&sx[r][0])[c4] = b;
    }
    __syncthreads();

    int lane = tid & 31;
    int grp  = tid >> 5;            // row-group: rows grp*8 .. grp*8+7

    float acc[8][CPT];
    #pragma unroll
    for (int r = 0; r < 8; r++)
        #pragma unroll
        for (int c = 0; c < CPT; c++) acc[r][c] = 0.0f;

    for (int k = 0; k < HIDF; k++) {
        float wl[CPT], wr[CPT];
        #pragma unroll
        for (int c = 0; c < CPT; c++) {
            int j = lane + c * 32;
            if (j < NC) {
                wl[c] = __ldg(&Wl[(size_t)k * NC + j]);
                wr[c] = __ldg(&Wr[(size_t)k * NC + j]);
            } else {
                wl[c] = 0.0f; wr[c] = 0.0f;
            }
        }
        #pragma unroll
        for (int r = 0; r < 8; r++) {
            float m  = sm[grp * 8 + r][k];
            float xv = sx[grp * 8 + r][k];
            #pragma unroll
            for (int c = 0; c < CPT; c++)
                acc[r][c] += m * wl[c] + xv * wr[c];
        }
    }

    #pragma unroll
    for (int r = 0; r < 8; r++) {
        int row = row0 + grp * 8 + r;
        if (row >= nrows) continue;
        #pragma unroll
        for (int c = 0; c < CPT; c++) {
            int j = lane + c * 32;
            if (j < NC) {
                float v = acc[r][c];
                if (bias) v += bias[j];
                out[(size_t)row * NC + j] = v;
            }
        }
    }
}

// ---------------- BN statistics: per-channel sum and sumsq ----------------
__global__ void bn_stats_kernel(const float* __restrict__ h, float* __restrict__ sums, int nrows) {
    int c = threadIdx.x;   // 128 channels
    float s = 0.0f, q = 0.0f;
    for (int r = blockIdx.x; r < nrows; r += gridDim.x) {
        float v = h[(size_t)r * HIDF + c];
        s += v; q += v * v;
    }
    atomicAdd(&sums[c], s);
    atomicAdd(&sums[HIDF + c], q);
}

// ---------------- BN apply + ReLU (in place) ----------------
__global__ void bn_apply_kernel(float* __restrict__ h, const float* __restrict__ sums,
                                const float* __restrict__ g, const float* __restrict__ be,
                                int total, int nrows) {
    int i = blockIdx.x * blockDim.x + threadIdx.x;
    if (i >= total) return;
    int c = i & (HIDF - 1);
    float invN = 1.0f / (float)nrows;
    float mu  = sums[c] * invN;
    float var = sums[HIDF + c] * invN - mu * mu;
    float v = (h[i] - mu) * rsqrtf(var + BN_EPS) * g[c] + be[c];
    h[i] = fmaxf(v, 0.0f);
}

// ---------------- launch ----------------
extern "C" void kernel_launch(void* const* d_in, const int* in_sizes, int n_in,
                              void* d_out, int out_size) {
    const float* x   = (const float*)d_in[0];
    const int*   ei  = (const int*)d_in[1];       // int32 (JAX x64 disabled)
    const float* Wl0 = (const float*)d_in[2];
    const float* Wr0 = (const float*)d_in[3];
    const float* Wl1 = (const float*)d_in[4];
    const float* Wr1 = (const float*)d_in[5];
    const float* Wl2 = (const float*)d_in[6];
    const float* Wr2 = (const float*)d_in[7];
    const float* b2  = (const float*)d_in[8];
    const float* g0  = (const float*)d_in[9];
    const float* be0 = (const float*)d_in[10];
    const float* g1  = (const float*)d_in[11];
    const float* be1 = (const float*)d_in[12];
    float* out = (float*)d_out;

    int E = in_sizes[1] / 2;
    int N = in_sizes[0] / HIDF;

    float *agg, *h0, *h1, *cnt, *sums;
    cudaGetSymbolAddress((void**)&agg,  g_agg);
    cudaGetSymbolAddress((void**)&h0,   g_h0);
    cudaGetSymbolAddress((void**)&h1,   g_h1);
    cudaGetSymbolAddress((void**)&cnt,  g_cnt);
    cudaGetSymbolAddress((void**)&sums, g_sums);

    const int FEAT4 = N * HIDF / 4;
    int scat_blocks = (int)(((long long)E * 32 + 255) / 256);
    int gemm_blocks = (N + 31) / 32;
    int zero_blocks = (FEAT4 + 255) / 256;
    int total = N * HIDF;

    // degree (shared by all layers)
    zero_small_kernel<<<(N + 255) / 256, 256>>>(cnt, N);
    degree_kernel<<<(E + 255) / 256, 256>>>(ei, cnt, E, N);

    // ---- layer 0 ----
    zero_kernel<<<zero_blocks, 256>>>((float4*)agg, FEAT4);
    scatter_kernel<<<scat_blocks, 256>>>(x, ei, agg, E, N);
    gemm_kernel<HIDF><<<gemm_blocks, 128>>>(agg, cnt, x, Wl0, Wr0, nullptr, h0, N);
    zero_small_kernel<<<1, 256>>>(sums, 2 * HIDF);
    bn_stats_kernel<<<512, HIDF>>>(h0, sums, N);
    bn_apply_kernel<<<(total + 255) / 256, 256>>>(h0, sums, g0, be0, total, N);

    // ---- layer 1 ----
    zero_kernel<<<zero_blocks, 256>>>((float4*)agg, FEAT4);
    scatter_kernel<<<scat_blocks, 256>>>(h0, ei, agg, E, N);
    gemm_kernel<HIDF><<<gemm_blocks, 128>>>(agg, cnt, h0, Wl1, Wr1, nullptr, h1, N);
    zero_small_kernel<<<1, 256>>>(sums, 2 * HIDF);
    bn_stats_kernel<<<512, HIDF>>>(h1, sums, N);
    bn_apply_kernel<<<(total + 255) / 256, 256>>>(h1, sums, g1, be1, total, N);

    // ---- layer 2 ----
    zero_kernel<<<zero_blocks, 256>>>((float4*)agg, FEAT4);
    scatter_kernel<<<scat_blocks, 256>>>(h1, ei, agg, E, N);
    gemm_kernel<OUTF><<<gemm_blocks, 128>>>(agg, cnt, h1, Wl2, Wr2, b2, out, N);
}

// round 4
// speedup vs baseline: 1.2452x; 1.2452x over previous
#include <cuda_runtime.h>
#include <cstdint>

#define N_NODES 100000
#define E_EDGES 800000
#define HIDF 128
#define OUTF 40
#define BN_EPS 1e-5f

// ---------------- scratch (no allocations allowed) ----------------
__device__ float g_agg[(size_t)N_NODES * HIDF];
__device__ float g_h0 [(size_t)N_NODES * HIDF];
__device__ float g_h1 [(size_t)N_NODES * HIDF];
__device__ float g_cnt[N_NODES];
__device__ float g_sums[2 * HIDF];

// ---------------- zero fill ----------------
__global__ void zero_kernel(float4* __restrict__ p, int n4) {
    int i = blockIdx.x * blockDim.x + threadIdx.x;
    if (i < n4) p[i] = make_float4(0.f, 0.f, 0.f, 0.f);
}
__global__ void zero_small_kernel(float* __restrict__ p, int n) {
    int i = blockIdx.x * blockDim.x + threadIdx.x;
    if (i < n) p[i] = 0.0f;
}

// ---------------- degree ----------------
__global__ void degree_kernel(const int* __restrict__ ei, float* __restrict__ cnt,
                              int E, int N) {
    int e = blockIdx.x * blockDim.x + threadIdx.x;
    if (e >= E) return;
    int d = ei[E + e];
    if ((unsigned)d < (unsigned)N) atomicAdd(&cnt[d], 1.0f);
}

// ---------------- scatter-add, 2 edges per thread (MLP=2) ----------------
__global__ void scatter_kernel(const float* __restrict__ feat,
                               const int* __restrict__ ei,
                               float* __restrict__ agg, int E, int N) {
    int idx = blockIdx.x * blockDim.x + threadIdx.x;
    int half = (E + 1) >> 1;
    int e1 = idx >> 5;
    if (e1 >= half) return;
    int e2 = e1 + half;
    int c = (idx & 31) << 2;

    int s1 = ei[e1], d1 = ei[E + e1];
    bool ok1 = (unsigned)s1 < (unsigned)N && (unsigned)d1 < (unsigned)N;
    bool has2 = e2 < E;
    int s2 = has2 ? ei[e2] : 0;
    int d2 = has2 ? ei[E + e2] : 0;
    bool ok2 = has2 && (unsigned)s2 < (unsigned)N && (unsigned)d2 < (unsigned)N;

    float4 v1 = make_float4(0.f,0.f,0.f,0.f), v2 = make_float4(0.f,0.f,0.f,0.f);
    if (ok1) v1 = *reinterpret_cast<const float4*>(feat + (size_t)s1 * HIDF + c);
    if (ok2) v2 = *reinterpret_cast<const float4*>(feat + (size_t)s2 * HIDF + c);

    if (ok1) {
        float* p = agg + (size_t)d1 * HIDF + c;
        asm volatile("red.global.add.v4.f32 [%0], {%1,%2,%3,%4};"
                     :: "l"(p), "f"(v1.x), "f"(v1.y), "f"(v1.z), "f"(v1.w) : "memory");
    }
    if (ok2) {
        float* p = agg + (size_t)d2 * HIDF + c;
        asm volatile("red.global.add.v4.f32 [%0], {%1,%2,%3,%4};"
                     :: "l"(p), "f"(v2.x), "f"(v2.y), "f"(v2.z), "f"(v2.w) : "memory");
    }
}

// ============ fast GEMM for NC=128: out = [mean|x](64x256) @ [Wl;Wr](256x128) ============
// 128 threads, thread tile 8 rows x 8 cols, packed fma.rn.f32x2 accumulators.
// smem: sA[64][256] (65536B) + sW[32][128] (16384B) + sInv[64] (256B)
#define GB_SMEM (64 * 256 * 4 + 32 * 128 * 4 + 64 * 4)

__device__ __forceinline__ unsigned long long pack2(float a) {
    unsigned long long r;
    asm("mov.b64 %0, {%1, %1};" : "=l"(r) : "f"(a));
    return r;
}
__device__ __forceinline__ void fma2(unsigned long long& acc, unsigned long long a,
                                     unsigned long long b) {
    asm("fma.rn.f32x2 %0, %1, %2, %0;" : "+l"(acc) : "l"(a), "l"(b));
}

__global__ void __launch_bounds__(128, 2)
gemm2_kernel(const float* __restrict__ agg,
             const float* __restrict__ cnt,
             const float* __restrict__ feat,
             const float* __restrict__ Wl,
             const float* __restrict__ Wr,
             float* __restrict__ out, int nrows) {
    extern __shared__ float smem[];
    float* sA   = smem;                 // [64][256]
    float* sW   = smem + 64 * 256;      // [32][128]
    float* sInv = sW + 32 * 128;        // [64]

    int tid  = threadIdx.x;
    int row0 = blockIdx.x * 64;

    if (tid < 64) {
        int r = row0 + tid;
        float c = (r < nrows) ? cnt[r] : 1.0f;
        sInv[tid] = 1.0f / fmaxf(c, 1.0f);
    }
    __syncthreads();

    // stage A = [mean | x]: 64 rows x 256 cols. 2048 float4 each half? -> interleave both.
    #pragma unroll
    for (int i = 0; i < 16; i++) {
        int idx4 = i * 128 + tid;          // [0,2048): 32 float4 per row per half
        int r    = idx4 >> 5;
        int c4   = idx4 & 31;
        int row  = row0 + r;
        float4 a = make_float4(0.f,0.f,0.f,0.f);
        float4 b = make_float4(0.f,0.f,0.f,0.f);
        if (row < nrows) {
            a = reinterpret_cast<const float4*>(agg  + (size_t)row * HIDF)[c4];
            b = reinterpret_cast<const float4*>(feat + (size_t)row * HIDF)[c4];
        }
        float iv = sInv[r];
        a.x *= iv; a.y *= iv; a.z *= iv; a.w *= iv;
        *reinterpret_cast<float4*>(sA + r * 256 + c4 * 4)       = a;
        *reinterpret_cast<float4*>(sA + r * 256 + 128 + c4 * 4) = b;
    }

    int tc = tid & 15;           // 16 col-groups: cols j0 = tc*8
    int tr = tid >> 4;           // 8 row-groups: rows r0 = tr*8
    int j0 = tc * 8;
    int r0 = tr * 8;

    unsigned long long acc[8][4];
    #pragma unroll
    for (int r = 0; r < 8; r++)
        #pragma unroll
        for (int c = 0; c < 4; c++) acc[r][c] = 0ull;

    // K loop: 8 tiles of 32 k. Tiles 0-3 from Wl (k in sA cols 0..127),
    // tiles 4-7 from Wr (k in sA cols 128..255).
    for (int kt = 0; kt < 8; kt++) {
        const float* Wsrc = (kt < 4) ? Wl : Wr;
        int kbase = (kt & 3) * 32;
        __syncthreads();
        // stage sW[32][128]: 1024 float4, 128 threads -> 8 each
        #pragma unroll
        for (int i = 0; i < 8; i++) {
            int idx4 = i * 128 + tid;      // 32 float4 per k-row
            int kk   = idx4 >> 5;
            int c4   = idx4 & 31;
            *reinterpret_cast<float4*>(sW + kk * 128 + c4 * 4) =
                *reinterpret_cast<const float4*>(Wsrc + (size_t)(kbase + kk) * 128 + c4 * 4);
        }
        __syncthreads();

        const float* sAk = sA + kt * 32;   // column offset for this tile
        #pragma unroll 8
        for (int kk = 0; kk < 32; kk++) {
            unsigned long long bp[4];
            const unsigned long long* bsrc =
                reinterpret_cast<const unsigned long long*>(sW + kk * 128 + j0);
            #pragma unroll
            for (int c = 0; c < 4; c++) bp[c] = bsrc[c];
            #pragma unroll
            for (int r = 0; r < 8; r++) {
                unsigned long long ap = pack2(sAk[(r0 + r) * 256 + kk]);
                #pragma unroll
                for (int c = 0; c < 4; c++) fma2(acc[r][c], ap, bp[c]);
            }
        }
    }

    // epilogue
    #pragma unroll
    for (int r = 0; r < 8; r++) {
        int row = row0 + r0 + r;
        if (row >= nrows) continue;
        float* po = out + (size_t)row * HIDF + j0;
        #pragma unroll
        for (int c = 0; c < 4; c++) {
            unsigned int lo, hi;
            asm("mov.b64 {%0, %1}, %2;" : "=r"(lo), "=r"(hi) : "l"(acc[r][c]));
            reinterpret_cast<float2*>(po)[c] =
                make_float2(__uint_as_float(lo), __uint_as_float(hi));
        }
    }
}

// ---------------- layer-2 GEMM (NC=40), proven path ----------------
template <int NC>
__global__ void gemm_kernel(const float* __restrict__ agg,
                            const float* __restrict__ cnt,
                            const float* __restrict__ feat,
                            const float* __restrict__ Wl,
                            const float* __restrict__ Wr,
                            const float* __restrict__ bias,
                            float* __restrict__ out, int nrows) {
    constexpr int CPT = (NC + 31) / 32;
    __shared__ float sm[32][HIDF];
    __shared__ float sx[32][HIDF];
    __shared__ float sinv[32];

    int tid  = threadIdx.x;
    int row0 = blockIdx.x * 32;

    if (tid < 32) {
        int r = row0 + tid;
        float c = (r < nrows) ? cnt[r] : 1.0f;
        sinv[tid] = 1.0f / fmaxf(c, 1.0f);
    }
    __syncthreads();

    #pragma unroll
    for (int i = 0; i < 8; i++) {
        int idx4 = i * 128 + tid;
        int r    = idx4 >> 5;
        int c4   = idx4 & 31;
        int row  = row0 + r;
        float4 a = make_float4(0.f,0.f,0.f,0.f);
        float4 b = make_float4(0.f,0.f,0.f,0.f);
        if (row < nrows) {
            a = reinterpret_cast<const float4*>(agg  + (size_t)row * HIDF)[c4];
            b = reinterpret_cast<const float4*>(feat + (size_t)row * HIDF)[c4];
        }
        float iv = sinv[r];
        a.x *= iv; a.y *= iv; a.z *= iv; a.w *= iv;
        reinterpret_cast<float4*>(&sm[r][0])[c4] = a;
        reinterpret_cast<float4*>(&sx[r][0])[c4] = b;
    }
    __syncthreads();

    int lane = tid & 31;
    int grp  = tid >> 5;

    float acc[8][CPT];
    #pragma unroll
    for (int r = 0; r < 8; r++)
        #pragma unroll
        for (int c = 0; c < CPT; c++) acc[r][c] = 0.0f;

    for (int k = 0; k < HIDF; k++) {
        float wl[CPT], wr[CPT];
        #pragma unroll
        for (int c = 0; c < CPT; c++) {
            int j = lane + c * 32;
            if (j < NC) {
                wl[c] = __ldg(&Wl[(size_t)k * NC + j]);
                wr[c] = __ldg(&Wr[(size_t)k * NC + j]);
            } else { wl[c] = 0.0f; wr[c] = 0.0f; }
        }
        #pragma unroll
        for (int r = 0; r < 8; r++) {
            float m  = sm[grp * 8 + r][k];
            float xv = sx[grp * 8 + r][k];
            #pragma unroll
            for (int c = 0; c < CPT; c++)
                acc[r][c] += m * wl[c] + xv * wr[c];
        }
    }

    #pragma unroll
    for (int r = 0; r < 8; r++) {
        int row = row0 + grp * 8 + r;
        if (row >= nrows) continue;
        #pragma unroll
        for (int c = 0; c < CPT; c++) {
            int j = lane + c * 32;
            if (j < NC) {
                float v = acc[r][c];
                if (bias) v += bias[j];
                out[(size_t)row * NC + j] = v;
            }
        }
    }
}

// ---------------- BN ----------------
__global__ void bn_stats_kernel(const float* __restrict__ h, float* __restrict__ sums, int nrows) {
    int c = threadIdx.x;
    float s = 0.0f, q = 0.0f;
    for (int r = blockIdx.x; r < nrows; r += gridDim.x) {
        float v = h[(size_t)r * HIDF + c];
        s += v; q += v * v;
    }
    atomicAdd(&sums[c], s);
    atomicAdd(&sums[HIDF + c], q);
}

__global__ void bn_apply_kernel(float* __restrict__ h, const float* __restrict__ sums,
                                const float* __restrict__ g, const float* __restrict__ be,
                                int total, int nrows) {
    int i = blockIdx.x * blockDim.x + threadIdx.x;
    if (i >= total) return;
    int c = i & (HIDF - 1);
    float invN = 1.0f / (float)nrows;
    float mu  = sums[c] * invN;
    float var = sums[HIDF + c] * invN - mu * mu;
    float v = (h[i] - mu) * rsqrtf(var + BN_EPS) * g[c] + be[c];
    h[i] = fmaxf(v, 0.0f);
}

// ---------------- launch ----------------
extern "C" void kernel_launch(void* const* d_in, const int* in_sizes, int n_in,
                              void* d_out, int out_size) {
    const float* x   = (const float*)d_in[0];
    const int*   ei  = (const int*)d_in[1];
    const float* Wl0 = (const float*)d_in[2];
    const float* Wr0 = (const float*)d_in[3];
    const float* Wl1 = (const float*)d_in[4];
    const float* Wr1 = (const float*)d_in[5];
    const float* Wl2 = (const float*)d_in[6];
    const float* Wr2 = (const float*)d_in[7];
    const float* b2  = (const float*)d_in[8];
    const float* g0  = (const float*)d_in[9];
    const float* be0 = (const float*)d_in[10];
    const float* g1  = (const float*)d_in[11];
    const float* be1 = (const float*)d_in[12];
    float* out = (float*)d_out;

    int E = in_sizes[1] / 2;
    int N = in_sizes[0] / HIDF;

    float *agg, *h0, *h1, *cnt, *sums;
    cudaGetSymbolAddress((void**)&agg,  g_agg);
    cudaGetSymbolAddress((void**)&h0,   g_h0);
    cudaGetSymbolAddress((void**)&h1,   g_h1);
    cudaGetSymbolAddress((void**)&cnt,  g_cnt);
    cudaGetSymbolAddress((void**)&sums, g_sums);

    static int smem_set = 0;
    if (!smem_set) {
        cudaFuncSetAttribute(gemm2_kernel,
                             cudaFuncAttributeMaxDynamicSharedMemorySize, GB_SMEM);
        smem_set = 1;
    }

    const int FEAT4 = N * HIDF / 4;
    int half = (E + 1) >> 1;
    int scat_blocks = (int)(((long long)half * 32 + 255) / 256);
    int g2_blocks   = (N + 63) / 64;
    int g40_blocks  = (N + 31) / 32;
    int zero_blocks = (FEAT4 + 255) / 256;
    int total = N * HIDF;

    zero_small_kernel<<<(N + 255) / 256, 256>>>(cnt, N);
    degree_kernel<<<(E + 255) / 256, 256>>>(ei, cnt, E, N);

    // ---- layer 0 ----
    zero_kernel<<<zero_blocks, 256>>>((float4*)agg, FEAT4);
    scatter_kernel<<<scat_blocks, 256>>>(x, ei, agg, E, N);
    gemm2_kernel<<<g2_blocks, 128, GB_SMEM>>>(agg, cnt, x, Wl0, Wr0, h0, N);
    zero_small_kernel<<<1, 256>>>(sums, 2 * HIDF);
    bn_stats_kernel<<<512, HIDF>>>(h0, sums, N);
    bn_apply_kernel<<<(total + 255) / 256, 256>>>(h0, sums, g0, be0, total, N);

    // ---- layer 1 ----
    zero_kernel<<<zero_blocks, 256>>>((float4*)agg, FEAT4);
    scatter_kernel<<<scat_blocks, 256>>>(h0, ei, agg, E, N);
    gemm2_kernel<<<g2_blocks, 128, GB_SMEM>>>(agg, cnt, h0, Wl1, Wr1, h1, N);
    zero_small_kernel<<<1, 256>>>(sums, 2 * HIDF);
    bn_stats_kernel<<<512, HIDF>>>(h1, sums, N);
    bn_apply_kernel<<<(total + 255) / 256, 256>>>(h1, sums, g1, be1, total, N);

    // ---- layer 2 ----
    zero_kernel<<<zero_blocks, 256>>>((float4*)agg, FEAT4);
    scatter_kernel<<<scat_blocks, 256>>>(h1, ei, agg, E, N);
    gemm_kernel<OUTF><<<g40_blocks, 128>>>(agg, cnt, h1, Wl2, Wr2, b2, out, N);
}

// round 5
// speedup vs baseline: 1.4625x; 1.1745x over previous
#include <cuda_runtime.h>
#include <cstdint>

#define N_NODES 100000
#define HIDF 128
#define OUTF 40
#define BN_EPS 1e-5f

// ---------------- scratch ----------------
__device__ float g_agg[(size_t)N_NODES * HIDF];
__device__ float g_h0 [(size_t)N_NODES * HIDF];
__device__ float g_h1 [(size_t)N_NODES * HIDF];
__device__ float g_cnt[N_NODES];
__device__ float g_sums[2 * HIDF];

// ---------------- zero fill ----------------
__global__ void zero_kernel(float4* __restrict__ p, int n4) {
    int i = blockIdx.x * blockDim.x + threadIdx.x;
    if (i < n4) p[i] = make_float4(0.f, 0.f, 0.f, 0.f);
}
__global__ void zero_small_kernel(float* __restrict__ p, int n) {
    int i = blockIdx.x * blockDim.x + threadIdx.x;
    if (i < n) p[i] = 0.0f;
}

// ---------------- degree ----------------
__global__ void degree_kernel(const int* __restrict__ ei, float* __restrict__ cnt,
                              int E, int N) {
    int e = blockIdx.x * blockDim.x + threadIdx.x;
    if (e >= E) return;
    int d = ei[E + e];
    if ((unsigned)d < (unsigned)N) atomicAdd(&cnt[d], 1.0f);
}

// ---------------- scatter-add, 2 edges per thread (MLP=2) ----------------
__global__ void scatter_kernel(const float* __restrict__ feat,
                               const int* __restrict__ ei,
                               float* __restrict__ agg, int E, int N) {
    int idx = blockIdx.x * blockDim.x + threadIdx.x;
    int half = (E + 1) >> 1;
    int e1 = idx >> 5;
    if (e1 >= half) return;
    int e2 = e1 + half;
    int c = (idx & 31) << 2;

    int s1 = ei[e1], d1 = ei[E + e1];
    bool ok1 = (unsigned)s1 < (unsigned)N && (unsigned)d1 < (unsigned)N;
    bool has2 = e2 < E;
    int s2 = has2 ? ei[e2] : 0;
    int d2 = has2 ? ei[E + e2] : 0;
    bool ok2 = has2 && (unsigned)s2 < (unsigned)N && (unsigned)d2 < (unsigned)N;

    float4 v1 = make_float4(0.f,0.f,0.f,0.f), v2 = make_float4(0.f,0.f,0.f,0.f);
    if (ok1) v1 = *reinterpret_cast<const float4*>(feat + (size_t)s1 * HIDF + c);
    if (ok2) v2 = *reinterpret_cast<const float4*>(feat + (size_t)s2 * HIDF + c);

    if (ok1) {
        float* p = agg + (size_t)d1 * HIDF + c;
        asm volatile("red.global.add.v4.f32 [%0], {%1,%2,%3,%4};"
                     :: "l"(p), "f"(v1.x), "f"(v1.y), "f"(v1.z), "f"(v1.w) : "memory");
    }
    if (ok2) {
        float* p = agg + (size_t)d2 * HIDF + c;
        asm volatile("red.global.add.v4.f32 [%0], {%1,%2,%3,%4};"
                     :: "l"(p), "f"(v2.x), "f"(v2.y), "f"(v2.z), "f"(v2.w) : "memory");
    }
}

// ================= tensor-core tf32 (3x-split) GEMM =================
// out[128rows x NC] = [mean|x](K=256) @ [Wl;Wr]   via m16n8k8 tf32 mma
#define SWA 36     // A smem row stride (floats): (4r+k)%32 distinct -> conflict-free
#define SWB 136    // B smem k-row stride (NC=128): (8k+n)%32 distinct
#define SWB40 40   // B smem k-row stride (NC=40)

__device__ __forceinline__ unsigned tf32_hi(float x) {
    unsigned h;
    asm("cvt.rna.tf32.f32 %0, %1;" : "=r"(h) : "f"(x));
    return h;
}

#define MMA_TF32(d, A0,A1,A2,A3, B0,B1) \
    asm volatile("mma.sync.aligned.m16n8k8.row.col.f32.tf32.tf32.f32 " \
        "{%0,%1,%2,%3}, {%4,%5,%6,%7}, {%8,%9}, {%0,%1,%2,%3};" \
        : "+f"((d)[0]), "+f"((d)[1]), "+f"((d)[2]), "+f"((d)[3]) \
        : "r"(A0), "r"(A1), "r"(A2), "r"(A3), "r"(B0), "r"(B1))

#define FB(p) __float_as_uint(p)

// smem (floats): Ahi[128*36] Alo[128*36] Bhi[32*136] Blo[32*136] inv[128]
#define TC128_SMEM ((128*SWA*2 + 32*SWB*2 + 128) * 4)

__global__ void __launch_bounds__(256)
gemm_tc128_kernel(const float* __restrict__ agg,
                  const float* __restrict__ cnt,
                  const float* __restrict__ feat,
                  const float* __restrict__ Wl,
                  const float* __restrict__ Wr,
                  float* __restrict__ out, int nrows) {
    extern __shared__ float sm[];
    float* sAhi = sm;
    float* sAlo = sAhi + 128 * SWA;
    float* sBhi = sAlo + 128 * SWA;
    float* sBlo = sBhi + 32 * SWB;
    float* sInv = sBlo + 32 * SWB;

    int tid  = threadIdx.x;
    int row0 = blockIdx.x * 128;
    int lane = tid & 31;
    int wid  = tid >> 5;
    int qr = lane >> 2, qc = lane & 3;
    int r0w = (wid & 3) * 32;     // warp row base
    int n0w = (wid >> 2) * 64;    // warp col base

    if (tid < 128) {
        int r = row0 + tid;
        float c = (r < nrows) ? cnt[r] : 1.0f;
        sInv[tid] = 1.0f / fmaxf(c, 1.0f);
    }
    __syncthreads();

    float acc[2][8][4];
    #pragma unroll
    for (int m = 0; m < 2; m++)
        #pragma unroll
        for (int n = 0; n < 8; n++)
            #pragma unroll
            for (int i = 0; i < 4; i++) acc[m][n][i] = 0.0f;

    for (int chunk = 0; chunk < 8; chunk++) {
        const float* asrc = (chunk < 4) ? agg : feat;
        const float* bsrc = (chunk < 4) ? Wl : Wr;
        bool scale = (chunk < 4);
        int kbase = (chunk & 3) * 32;

        // stage A: 128 rows x 32 k  (1024 float4, 4 per thread)
        #pragma unroll
        for (int i = 0; i < 4; i++) {
            int idx4 = i * 256 + tid;
            int r  = idx4 >> 3;
            int c4 = idx4 & 7;
            int row = row0 + r;
            float4 v = make_float4(0.f,0.f,0.f,0.f);
            if (row < nrows)
                v = *reinterpret_cast<const float4*>(asrc + (size_t)row * HIDF + kbase + 4*c4);
            if (scale) { float iv = sInv[r]; v.x*=iv; v.y*=iv; v.z*=iv; v.w*=iv; }
            float4 h, l;
            h.x = __uint_as_float(tf32_hi(v.x)); l.x = v.x - h.x;
            h.y = __uint_as_float(tf32_hi(v.y)); l.y = v.y - h.y;
            h.z = __uint_as_float(tf32_hi(v.z)); l.z = v.z - h.z;
            h.w = __uint_as_float(tf32_hi(v.w)); l.w = v.w - h.w;
            *reinterpret_cast<float4*>(sAhi + r * SWA + 4*c4) = h;
            *reinterpret_cast<float4*>(sAlo + r * SWA + 4*c4) = l;
        }
        // stage B: 32 k x 128 n  (1024 float4, 4 per thread)
        #pragma unroll
        for (int i = 0; i < 4; i++) {
            int idx4 = i * 256 + tid;
            int kk = idx4 >> 5;
            int c4 = idx4 & 31;
            float4 v = *reinterpret_cast<const float4*>(bsrc + (size_t)(kbase + kk) * 128 + 4*c4);
            float4 h, l;
            h.x = __uint_as_float(tf32_hi(v.x)); l.x = v.x - h.x;
            h.y = __uint_as_float(tf32_hi(v.y)); l.y = v.y - h.y;
            h.z = __uint_as_float(tf32_hi(v.z)); l.z = v.z - h.z;
            h.w = __uint_as_float(tf32_hi(v.w)); l.w = v.w - h.w;
            *reinterpret_cast<float4*>(sBhi + kk * SWB + 4*c4) = h;
            *reinterpret_cast<float4*>(sBlo + kk * SWB + 4*c4) = l;
        }
        __syncthreads();

        for (int ks = 0; ks < 4; ks++) {
            int kk = ks * 8;
            unsigned ah[2][4], al[2][4];
            #pragma unroll
            for (int mt = 0; mt < 2; mt++) {
                const float* pa = sAhi + (r0w + mt*16 + qr) * SWA + kk + qc;
                ah[mt][0] = FB(pa[0]);       ah[mt][1] = FB(pa[8*SWA]);
                ah[mt][2] = FB(pa[4]);       ah[mt][3] = FB(pa[8*SWA + 4]);
                const float* pl = sAlo + (r0w + mt*16 + qr) * SWA + kk + qc;
                al[mt][0] = FB(pl[0]);       al[mt][1] = FB(pl[8*SWA]);
                al[mt][2] = FB(pl[4]);       al[mt][3] = FB(pl[8*SWA + 4]);
            }
            #pragma unroll
            for (int nt = 0; nt < 8; nt++) {
                int col = n0w + nt*8 + qr;
                const float* pb = sBhi + (kk + qc) * SWB + col;
                unsigned bh0 = FB(pb[0]), bh1 = FB(pb[4*SWB]);
                const float* pq = sBlo + (kk + qc) * SWB + col;
                unsigned bl0 = FB(pq[0]), bl1 = FB(pq[4*SWB]);
                #pragma unroll
                for (int mt = 0; mt < 2; mt++) {
                    MMA_TF32(acc[mt][nt], ah[mt][0],ah[mt][1],ah[mt][2],ah[mt][3], bh0,bh1);
                    MMA_TF32(acc[mt][nt], ah[mt][0],ah[mt][1],ah[mt][2],ah[mt][3], bl0,bl1);
                    MMA_TF32(acc[mt][nt], al[mt][0],al[mt][1],al[mt][2],al[mt][3], bh0,bh1);
                }
            }
        }
        __syncthreads();
    }

    // epilogue: c0,c1 at (row, 2qc..), c2,c3 at (row+8, ..)
    #pragma unroll
    for (int mt = 0; mt < 2; mt++) {
        int rowa = row0 + r0w + mt*16 + qr;
        int rowb = rowa + 8;
        #pragma unroll
        for (int nt = 0; nt < 8; nt++) {
            int col = n0w + nt*8 + 2*qc;
            if (rowa < nrows)
                *reinterpret_cast<float2*>(out + (size_t)rowa * HIDF + col) =
                    make_float2(acc[mt][nt][0], acc[mt][nt][1]);
            if (rowb < nrows)
                *reinterpret_cast<float2*>(out + (size_t)rowb * HIDF + col) =
                    make_float2(acc[mt][nt][2], acc[mt][nt][3]);
        }
    }
}

// ---- NC=40 variant: 8 warps x 16 rows, 5 n-tiles, + bias ----
#define TC40_SMEM ((128*SWA*2 + 32*SWB40*2 + 128) * 4)

__global__ void __launch_bounds__(256)
gemm_tc40_kernel(const float* __restrict__ agg,
                 const float* __restrict__ cnt,
                 const float* __restrict__ feat,
                 const float* __restrict__ Wl,
                 const float* __restrict__ Wr,
                 const float* __restrict__ bias,
                 float* __restrict__ out, int nrows) {
    extern __shared__ float sm[];
    float* sAhi = sm;
    float* sAlo = sAhi + 128 * SWA;
    float* sBhi = sAlo + 128 * SWA;
    float* sBlo = sBhi + 32 * SWB40;
    float* sInv = sBlo + 32 * SWB40;

    int tid  = threadIdx.x;
    int row0 = blockIdx.x * 128;
    int lane = tid & 31;
    int wid  = tid >> 5;
    int qr = lane >> 2, qc = lane & 3;
    int r0w = wid * 16;

    if (tid < 128) {
        int r = row0 + tid;
        float c = (r < nrows) ? cnt[r] : 1.0f;
        sInv[tid] = 1.0f / fmaxf(c, 1.0f);
    }
    __syncthreads();

    float acc[5][4];
    #pragma unroll
    for (int n = 0; n < 5; n++)
        #pragma unroll
        for (int i = 0; i < 4; i++) acc[n][i] = 0.0f;

    for (int chunk = 0; chunk < 8; chunk++) {
        const float* asrc = (chunk < 4) ? agg : feat;
        const float* bsrc = (chunk < 4) ? Wl : Wr;
        bool scale = (chunk < 4);
        int kbase = (chunk & 3) * 32;

        #pragma unroll
        for (int i = 0; i < 4; i++) {
            int idx4 = i * 256 + tid;
            int r  = idx4 >> 3;
            int c4 = idx4 & 7;
            int row = row0 + r;
            float4 v = make_float4(0.f,0.f,0.f,0.f);
            if (row < nrows)
                v = *reinterpret_cast<const float4*>(asrc + (size_t)row * HIDF + kbase + 4*c4);
            if (scale) { float iv = sInv[r]; v.x*=iv; v.y*=iv; v.z*=iv; v.w*=iv; }
            float4 h, l;
            h.x = __uint_as_float(tf32_hi(v.x)); l.x = v.x - h.x;
            h.y = __uint_as_float(tf32_hi(v.y)); l.y = v.y - h.y;
            h.z = __uint_as_float(tf32_hi(v.z)); l.z = v.z - h.z;
            h.w = __uint_as_float(tf32_hi(v.w)); l.w = v.w - h.w;
            *reinterpret_cast<float4*>(sAhi + r * SWA + 4*c4) = h;
            *reinterpret_cast<float4*>(sAlo + r * SWA + 4*c4) = l;
        }
        // stage B: 32 k x 40 n = 1280 floats, exactly 5 per thread
        #pragma unroll
        for (int i = 0; i < 5; i++) {
            int idx = i * 256 + tid;
            int kk = idx / 40;
            int n  = idx % 40;
            float v = bsrc[(size_t)(kbase + kk) * OUTF + n];
            float h = __uint_as_float(tf32_hi(v));
            sBhi[kk * SWB40 + n] = h;
            sBlo[kk * SWB40 + n] = v - h;
        }
        __syncthreads();

        for (int ks = 0; ks < 4; ks++) {
            int kk = ks * 8;
            const float* pa = sAhi + (r0w + qr) * SWA + kk + qc;
            unsigned a0 = FB(pa[0]), a1 = FB(pa[8*SWA]), a2 = FB(pa[4]), a3 = FB(pa[8*SWA+4]);
            const float* pl = sAlo + (r0w + qr) * SWA + kk + qc;
            unsigned l0 = FB(pl[0]), l1 = FB(pl[8*SWA]), l2 = FB(pl[4]), l3 = FB(pl[8*SWA+4]);
            #pragma unroll
            for (int nt = 0; nt < 5; nt++) {
                int col = nt*8 + qr;
                const float* pb = sBhi + (kk + qc) * SWB40 + col;
                unsigned bh0 = FB(pb[0]), bh1 = FB(pb[4*SWB40]);
                const float* pq = sBlo + (kk + qc) * SWB40 + col;
                unsigned bl0 = FB(pq[0]), bl1 = FB(pq[4*SWB40]);
                MMA_TF32(acc[nt], a0,a1,a2,a3, bh0,bh1);
                MMA_TF32(acc[nt], a0,a1,a2,a3, bl0,bl1);
                MMA_TF32(acc[nt], l0,l1,l2,l3, bh0,bh1);
            }
        }
        __syncthreads();
    }

    int rowa = row0 + r0w + qr;
    int rowb = rowa + 8;
    #pragma unroll
    for (int nt = 0; nt < 5; nt++) {
        int col = nt*8 + 2*qc;
        float b0 = bias[col], b1 = bias[col+1];
        if (rowa < nrows)
            *reinterpret_cast<float2*>(out + (size_t)rowa * OUTF + col) =
                make_float2(acc[nt][0] + b0, acc[nt][1] + b1);
        if (rowb < nrows)
            *reinterpret_cast<float2*>(out + (size_t)rowb * OUTF + col) =
                make_float2(acc[nt][2] + b0, acc[nt][3] + b1);
    }
}

// ---------------- BN ----------------
__global__ void bn_stats_kernel(const float* __restrict__ h, float* __restrict__ sums, int nrows) {
    int c = threadIdx.x;
    float s = 0.0f, q = 0.0f;
    for (int r = blockIdx.x; r < nrows; r += gridDim.x) {
        float v = h[(size_t)r * HIDF + c];
        s += v; q += v * v;
    }
    atomicAdd(&sums[c], s);
    atomicAdd(&sums[HIDF + c], q);
}

__global__ void bn_apply_kernel(float* __restrict__ h, const float* __restrict__ sums,
                                const float* __restrict__ g, const float* __restrict__ be,
                                int total, int nrows) {
    int i = blockIdx.x * blockDim.x + threadIdx.x;
    if (i >= total) return;
    int c = i & (HIDF - 1);
    float invN = 1.0f / (float)nrows;
    float mu  = sums[c] * invN;
    float var = sums[HIDF + c] * invN - mu * mu;
    float v = (h[i] - mu) * rsqrtf(var + BN_EPS) * g[c] + be[c];
    h[i] = fmaxf(v, 0.0f);
}

// ---------------- launch ----------------
extern "C" void kernel_launch(void* const* d_in, const int* in_sizes, int n_in,
                              void* d_out, int out_size) {
    const float* x   = (const float*)d_in[0];
    const int*   ei  = (const int*)d_in[1];
    const float* Wl0 = (const float*)d_in[2];
    const float* Wr0 = (const float*)d_in[3];
    const float* Wl1 = (const float*)d_in[4];
    const float* Wr1 = (const float*)d_in[5];
    const float* Wl2 = (const float*)d_in[6];
    const float* Wr2 = (const float*)d_in[7];
    const float* b2  = (const float*)d_in[8];
    const float* g0  = (const float*)d_in[9];
    const float* be0 = (const float*)d_in[10];
    const float* g1  = (const float*)d_in[11];
    const float* be1 = (const float*)d_in[12];
    float* out = (float*)d_out;

    int E = in_sizes[1] / 2;
    int N = in_sizes[0] / HIDF;

    float *agg, *h0, *h1, *cnt, *sums;
    cudaGetSymbolAddress((void**)&agg,  g_agg);
    cudaGetSymbolAddress((void**)&h0,   g_h0);
    cudaGetSymbolAddress((void**)&h1,   g_h1);
    cudaGetSymbolAddress((void**)&cnt,  g_cnt);
    cudaGetSymbolAddress((void**)&sums, g_sums);

    static int smem_set = 0;
    if (!smem_set) {
        cudaFuncSetAttribute(gemm_tc128_kernel,
                             cudaFuncAttributeMaxDynamicSharedMemorySize, TC128_SMEM);
        cudaFuncSetAttribute(gemm_tc40_kernel,
                             cudaFuncAttributeMaxDynamicSharedMemorySize, TC40_SMEM);
        smem_set = 1;
    }

    const int FEAT4 = N * HIDF / 4;
    int half = (E + 1) >> 1;
    int scat_blocks = (int)(((long long)half * 32 + 255) / 256);
    int tc_blocks   = (N + 127) / 128;
    int zero_blocks = (FEAT4 + 255) / 256;
    int total = N * HIDF;

    zero_small_kernel<<<(N + 255) / 256, 256>>>(cnt, N);
    degree_kernel<<<(E + 255) / 256, 256>>>(ei, cnt, E, N);

    // ---- layer 0 ----
    zero_kernel<<<zero_blocks, 256>>>((float4*)agg, FEAT4);
    scatter_kernel<<<scat_blocks, 256>>>(x, ei, agg, E, N);
    gemm_tc128_kernel<<<tc_blocks, 256, TC128_SMEM>>>(agg, cnt, x, Wl0, Wr0, h0, N);
    zero_small_kernel<<<1, 256>>>(sums, 2 * HIDF);
    bn_stats_kernel<<<512, HIDF>>>(h0, sums, N);
    bn_apply_kernel<<<(total + 255) / 256, 256>>>(h0, sums, g0, be0, total, N);

    // ---- layer 1 ----
    zero_kernel<<<zero_blocks, 256>>>((float4*)agg, FEAT4);
    scatter_kernel<<<scat_blocks, 256>>>(h0, ei, agg, E, N);
    gemm_tc128_kernel<<<tc_blocks, 256, TC128_SMEM>>>(agg, cnt, h0, Wl1, Wr1, h1, N);
    zero_small_kernel<<<1, 256>>>(sums, 2 * HIDF);
    bn_stats_kernel<<<512, HIDF>>>(h1, sums, N);
    bn_apply_kernel<<<(total + 255) / 256, 256>>>(h1, sums, g1, be1, total, N);

    // ---- layer 2 ----
    zero_kernel<<<zero_blocks, 256>>>((float4*)agg, FEAT4);
    scatter_kernel<<<scat_blocks, 256>>>(h1, ei, agg, E, N);
    gemm_tc40_kernel<<<tc_blocks, 256, TC40_SMEM>>>(agg, cnt, h1, Wl2, Wr2, b2, out, N);
}

// round 6
// speedup vs baseline: 1.8112x; 1.2385x over previous
#include <cuda_runtime.h>
#include <cstdint>

#define N_NODES 100000
#define HIDF 128
#define OUTF 40
#define BN_EPS 1e-5f

// ---------------- scratch ----------------
__device__ float g_agg[(size_t)N_NODES * HIDF];
__device__ float g_h0 [(size_t)N_NODES * HIDF];
__device__ float g_h1 [(size_t)N_NODES * HIDF];
__device__ float g_cnt[N_NODES];
__device__ float g_sums[512];     // [layer][s:128 | q:128]
__device__ float g_bnp0[256];     // scale[128] | shift[128]
__device__ float g_bnp1[256];

// ---------------- zero fill ----------------
__global__ void zero_kernel(float4* __restrict__ p, int n4) {
    int i = blockIdx.x * blockDim.x + threadIdx.x;
    if (i < n4) p[i] = make_float4(0.f, 0.f, 0.f, 0.f);
}
__global__ void zero_small_kernel(float* __restrict__ p, int n) {
    int i = blockIdx.x * blockDim.x + threadIdx.x;
    if (i < n) p[i] = 0.0f;
}

// ---------------- degree ----------------
__global__ void degree_kernel(const int* __restrict__ ei, float* __restrict__ cnt,
                              int E, int N) {
    int e = blockIdx.x * blockDim.x + threadIdx.x;
    if (e >= E) return;
    int d = ei[E + e];
    if ((unsigned)d < (unsigned)N) atomicAdd(&cnt[d], 1.0f);
}

// ---------------- scatter-add, 4 edges per thread (MLP=4), optional fused BN+ReLU ----
__global__ void scatter_kernel(const float* __restrict__ feat,
                               const int* __restrict__ ei,
                               const float* __restrict__ bnp,
                               float* __restrict__ agg, int E, int N) {
    int idx = blockIdx.x * blockDim.x + threadIdx.x;
    int quarter = (E + 3) >> 2;
    int e0 = idx >> 5;
    if (e0 >= quarter) return;
    int c = (idx & 31) << 2;

    float4 sc4 = make_float4(1.f,1.f,1.f,1.f), sh4 = make_float4(0.f,0.f,0.f,0.f);
    bool bn = (bnp != nullptr);
    if (bn) {
        sc4 = *reinterpret_cast<const float4*>(bnp + c);
        sh4 = *reinterpret_cast<const float4*>(bnp + 128 + c);
    }

    int s[4], d[4]; bool ok[4];
    #pragma unroll
    for (int i = 0; i < 4; i++) {
        int e = e0 + i * quarter;
        bool has = e < E;
        s[i] = has ? ei[e] : 0;
        d[i] = has ? ei[E + e] : 0;
        ok[i] = has && (unsigned)s[i] < (unsigned)N && (unsigned)d[i] < (unsigned)N;
    }
    float4 v[4];
    #pragma unroll
    for (int i = 0; i < 4; i++)
        v[i] = ok[i] ? *reinterpret_cast<const float4*>(feat + (size_t)s[i] * HIDF + c)
                     : make_float4(0.f,0.f,0.f,0.f);
    if (bn) {
        #pragma unroll
        for (int i = 0; i < 4; i++) {
            v[i].x = fmaxf(fmaf(v[i].x, sc4.x, sh4.x), 0.f);
            v[i].y = fmaxf(fmaf(v[i].y, sc4.y, sh4.y), 0.f);
            v[i].z = fmaxf(fmaf(v[i].z, sc4.z, sh4.z), 0.f);
            v[i].w = fmaxf(fmaf(v[i].w, sc4.w, sh4.w), 0.f);
        }
    }
    #pragma unroll
    for (int i = 0; i < 4; i++) {
        if (ok[i]) {
            float* p = agg + (size_t)d[i] * HIDF + c;
            asm volatile("red.global.add.v4.f32 [%0], {%1,%2,%3,%4};"
                         :: "l"(p), "f"(v[i].x), "f"(v[i].y), "f"(v[i].z), "f"(v[i].w)
                         : "memory");
        }
    }
}

// ================= tensor-core tf32 (3x-split) GEMM =================
#define SWA 36
#define SWB 136
#define SWB40 40

__device__ __forceinline__ unsigned tf32_hi(float x) {
    unsigned h;
    asm("cvt.rna.tf32.f32 %0, %1;" : "=r"(h) : "f"(x));
    return h;
}

#define MMA_TF32(d, A0,A1,A2,A3, B0,B1) \
    asm volatile("mma.sync.aligned.m16n8k8.row.col.f32.tf32.tf32.f32 " \
        "{%0,%1,%2,%3}, {%4,%5,%6,%7}, {%8,%9}, {%0,%1,%2,%3};" \
        : "+f"((d)[0]), "+f"((d)[1]), "+f"((d)[2]), "+f"((d)[3]) \
        : "r"(A0), "r"(A1), "r"(A2), "r"(A3), "r"(B0), "r"(B1))

#define FB(p) __float_as_uint(p)

__device__ __forceinline__ void redg_f32(float* p, float v) {
    asm volatile("red.global.add.f32 [%0], %1;" :: "l"(p), "f"(v) : "memory");
}

// smem floats: Ahi[128*36] Alo[128*36] Bhi[32*136] Blo[32*136] inv[128] bn[256]
#define TC128_SMEM ((128*SWA*2 + 32*SWB*2 + 128 + 256) * 4)

__global__ void __launch_bounds__(256)
gemm_tc128_kernel(const float* __restrict__ agg,
                  const float* __restrict__ cnt,
                  const float* __restrict__ feat,
                  const float* __restrict__ bnp,   // affine for feat (null = raw)
                  const float* __restrict__ Wl,
                  const float* __restrict__ Wr,
                  float* __restrict__ out,
                  float* __restrict__ stats,        // [s:128|q:128] red.add target
                  int nrows) {
    extern __shared__ float sm[];
    float* sAhi = sm;
    float* sAlo = sAhi + 128 * SWA;
    float* sBhi = sAlo + 128 * SWA;
    float* sBlo = sBhi + 32 * SWB;
    float* sInv = sBlo + 32 * SWB;
    float* sBn  = sInv + 128;

    int tid  = threadIdx.x;
    int row0 = blockIdx.x * 128;
    int lane = tid & 31;
    int wid  = tid >> 5;
    int qr = lane >> 2, qc = lane & 3;
    int r0w = (wid & 3) * 32;
    int n0w = (wid >> 2) * 64;
    bool hasbn = (bnp != nullptr);

    if (tid < 128) {
        int r = row0 + tid;
        float c = (r < nrows) ? cnt[r] : 1.0f;
        sInv[tid] = 1.0f / fmaxf(c, 1.0f);
    } else if (hasbn) {
        sBn[tid - 128] = bnp[tid - 128];
        sBn[tid]       = bnp[tid];
    }
    __syncthreads();

    float acc[2][8][4];
    #pragma unroll
    for (int m = 0; m < 2; m++)
        #pragma unroll
        for (int n = 0; n < 8; n++)
            #pragma unroll
            for (int i = 0; i < 4; i++) acc[m][n][i] = 0.0f;

    for (int chunk = 0; chunk < 8; chunk++) {
        const float* asrc = (chunk < 4) ? agg : feat;
        const float* bsrc = (chunk < 4) ? Wl : Wr;
        bool isagg = (chunk < 4);
        int kbase = (chunk & 3) * 32;

        #pragma unroll
        for (int i = 0; i < 4; i++) {
            int idx4 = i * 256 + tid;
            int r  = idx4 >> 3;
            int c4 = idx4 & 7;
            int row = row0 + r;
            float4 v = make_float4(0.f,0.f,0.f,0.f);
            if (row < nrows) {
                v = *reinterpret_cast<const float4*>(asrc + (size_t)row * HIDF + kbase + 4*c4);
                if (isagg) {
                    float iv = sInv[r];
                    v.x*=iv; v.y*=iv; v.z*=iv; v.w*=iv;
                } else if (hasbn) {
                    int cc = kbase + 4*c4;
                    v.x = fmaxf(fmaf(v.x, sBn[cc+0], sBn[128+cc+0]), 0.f);
                    v.y = fmaxf(fmaf(v.y, sBn[cc+1], sBn[128+cc+1]), 0.f);
                    v.z = fmaxf(fmaf(v.z, sBn[cc+2], sBn[128+cc+2]), 0.f);
                    v.w = fmaxf(fmaf(v.w, sBn[cc+3], sBn[128+cc+3]), 0.f);
                }
            }
            float4 h, l;
            h.x = __uint_as_float(tf32_hi(v.x)); l.x = v.x - h.x;
            h.y = __uint_as_float(tf32_hi(v.y)); l.y = v.y - h.y;
            h.z = __uint_as_float(tf32_hi(v.z)); l.z = v.z - h.z;
            h.w = __uint_as_float(tf32_hi(v.w)); l.w = v.w - h.w;
            *reinterpret_cast<float4*>(sAhi + r * SWA + 4*c4) = h;
            *reinterpret_cast<float4*>(sAlo + r * SWA + 4*c4) = l;
        }
        #pragma unroll
        for (int i = 0; i < 4; i++) {
            int idx4 = i * 256 + tid;
            int kk = idx4 >> 5;
            int c4 = idx4 & 31;
            float4 v = *reinterpret_cast<const float4*>(bsrc + (size_t)(kbase + kk) * 128 + 4*c4);
            float4 h, l;
            h.x = __uint_as_float(tf32_hi(v.x)); l.x = v.x - h.x;
            h.y = __uint_as_float(tf32_hi(v.y)); l.y = v.y - h.y;
            h.z = __uint_as_float(tf32_hi(v.z)); l.z = v.z - h.z;
            h.w = __uint_as_float(tf32_hi(v.w)); l.w = v.w - h.w;
            *reinterpret_cast<float4*>(sBhi + kk * SWB + 4*c4) = h;
            *reinterpret_cast<float4*>(sBlo + kk * SWB + 4*c4) = l;
        }
        __syncthreads();

        for (int ks = 0; ks < 4; ks++) {
            int kk = ks * 8;
            unsigned ah[2][4], al[2][4];
            #pragma unroll
            for (int mt = 0; mt < 2; mt++) {
                const float* pa = sAhi + (r0w + mt*16 + qr) * SWA + kk + qc;
                ah[mt][0] = FB(pa[0]);  ah[mt][1] = FB(pa[8*SWA]);
                ah[mt][2] = FB(pa[4]);  ah[mt][3] = FB(pa[8*SWA + 4]);
                const float* pl = sAlo + (r0w + mt*16 + qr) * SWA + kk + qc;
                al[mt][0] = FB(pl[0]);  al[mt][1] = FB(pl[8*SWA]);
                al[mt][2] = FB(pl[4]);  al[mt][3] = FB(pl[8*SWA + 4]);
            }
            #pragma unroll
            for (int nt = 0; nt < 8; nt++) {
                int col = n0w + nt*8 + qr;
                const float* pb = sBhi + (kk + qc) * SWB + col;
                unsigned bh0 = FB(pb[0]), bh1 = FB(pb[4*SWB]);
                const float* pq = sBlo + (kk + qc) * SWB + col;
                unsigned bl0 = FB(pq[0]), bl1 = FB(pq[4*SWB]);
                #pragma unroll
                for (int mt = 0; mt < 2; mt++) {
                    MMA_TF32(acc[mt][nt], ah[mt][0],ah[mt][1],ah[mt][2],ah[mt][3], bh0,bh1);
                    MMA_TF32(acc[mt][nt], ah[mt][0],ah[mt][1],ah[mt][2],ah[mt][3], bl0,bl1);
                    MMA_TF32(acc[mt][nt], al[mt][0],al[mt][1],al[mt][2],al[mt][3], bh0,bh1);
                }
            }
        }
        __syncthreads();
    }

    // write out
    #pragma unroll
    for (int mt = 0; mt < 2; mt++) {
        int rowa = row0 + r0w + mt*16 + qr;
        int rowb = rowa + 8;
        #pragma unroll
        for (int nt = 0; nt < 8; nt++) {
            int col = n0w + nt*8 + 2*qc;
            if (rowa < nrows)
                *reinterpret_cast<float2*>(out + (size_t)rowa * HIDF + col) =
                    make_float2(acc[mt][nt][0], acc[mt][nt][1]);
            if (rowb < nrows)
                *reinterpret_cast<float2*>(out + (size_t)rowb * HIDF + col) =
                    make_float2(acc[mt][nt][2], acc[mt][nt][3]);
        }
    }

    // fused BN statistics: per-column sum/sumsq over this block's 128 rows.
    // (invalid rows have acc == 0 -> contribute nothing)
    #pragma unroll
    for (int nt = 0; nt < 8; nt++) {
        #pragma unroll
        for (int p = 0; p < 2; p++) {
            float v0 = acc[0][nt][p],   v1 = acc[0][nt][p+2];
            float v2 = acc[1][nt][p],   v3 = acc[1][nt][p+2];
            float s = v0 + v1 + v2 + v3;
            float q = v0*v0 + v1*v1 + v2*v2 + v3*v3;
            #pragma unroll
            for (int off = 4; off < 32; off <<= 1) {
                s += __shfl_xor_sync(0xffffffff, s, off);
                q += __shfl_xor_sync(0xffffffff, q, off);
            }
            if (qr == 0) {
                int col = n0w + nt*8 + 2*qc + p;
                redg_f32(stats + col, s);
                redg_f32(stats + 128 + col, q);
            }
        }
    }
}

// ---- bn finalize: sums -> per-channel scale/shift ----
__global__ void bn_finalize_kernel(const float* __restrict__ stats,
                                   const float* __restrict__ g,
                                   const float* __restrict__ be,
                                   float* __restrict__ bnp, int nrows) {
    int c = threadIdx.x;
    float invN = 1.0f / (float)nrows;
    float mu  = stats[c] * invN;
    float var = stats[128 + c] * invN - mu * mu;
    float sc  = g[c] * rsqrtf(var + BN_EPS);
    bnp[c]       = sc;
    bnp[128 + c] = be[c] - mu * sc;
}

// ---- NC=40 variant: 8 warps x 16 rows, 5 n-tiles, + bias, fused BN on feat ----
#define TC40_SMEM ((128*SWA*2 + 32*SWB40*2 + 128 + 256) * 4)

__global__ void __launch_bounds__(256)
gemm_tc40_kernel(const float* __restrict__ agg,
                 const float* __restrict__ cnt,
                 const float* __restrict__ feat,
                 const float* __restrict__ bnp,
                 const float* __restrict__ Wl,
                 const float* __restrict__ Wr,
                 const float* __restrict__ bias,
                 float* __restrict__ out, int nrows) {
    extern __shared__ float sm[];
    float* sAhi = sm;
    float* sAlo = sAhi + 128 * SWA;
    float* sBhi = sAlo + 128 * SWA;
    float* sBlo = sBhi + 32 * SWB40;
    float* sInv = sBlo + 32 * SWB40;
    float* sBn  = sInv + 128;

    int tid  = threadIdx.x;
    int row0 = blockIdx.x * 128;
    int lane = tid & 31;
    int wid  = tid >> 5;
    int qr = lane >> 2, qc = lane & 3;
    int r0w = wid * 16;

    if (tid < 128) {
        int r = row0 + tid;
        float c = (r < nrows) ? cnt[r] : 1.0f;
        sInv[tid] = 1.0f / fmaxf(c, 1.0f);
    } else {
        sBn[tid - 128] = bnp[tid - 128];
        sBn[tid]       = bnp[tid];
    }
    __syncthreads();

    float acc[5][4];
    #pragma unroll
    for (int n = 0; n < 5; n++)
        #pragma unroll
        for (int i = 0; i < 4; i++) acc[n][i] = 0.0f;

    for (int chunk = 0; chunk < 8; chunk++) {
        const float* asrc = (chunk < 4) ? agg : feat;
        const float* bsrc = (chunk < 4) ? Wl : Wr;
        bool isagg = (chunk < 4);
        int kbase = (chunk & 3) * 32;

        #pragma unroll
        for (int i = 0; i < 4; i++) {
            int idx4 = i * 256 + tid;
            int r  = idx4 >> 3;
            int c4 = idx4 & 7;
            int row = row0 + r;
            float4 v = make_float4(0.f,0.f,0.f,0.f);
            if (row < nrows) {
                v = *reinterpret_cast<const float4*>(asrc + (size_t)row * HIDF + kbase + 4*c4);
                if (isagg) {
                    float iv = sInv[r];
                    v.x*=iv; v.y*=iv; v.z*=iv; v.w*=iv;
                } else {
                    int cc = kbase + 4*c4;
                    v.x = fmaxf(fmaf(v.x, sBn[cc+0], sBn[128+cc+0]), 0.f);
                    v.y = fmaxf(fmaf(v.y, sBn[cc+1], sBn[128+cc+1]), 0.f);
                    v.z = fmaxf(fmaf(v.z, sBn[cc+2], sBn[128+cc+2]), 0.f);
                    v.w = fmaxf(fmaf(v.w, sBn[cc+3], sBn[128+cc+3]), 0.f);
                }
            }
            float4 h, l;
            h.x = __uint_as_float(tf32_hi(v.x)); l.x = v.x - h.x;
            h.y = __uint_as_float(tf32_hi(v.y)); l.y = v.y - h.y;
            h.z = __uint_as_float(tf32_hi(v.z)); l.z = v.z - h.z;
            h.w = __uint_as_float(tf32_hi(v.w)); l.w = v.w - h.w;
            *reinterpret_cast<float4*>(sAhi + r * SWA + 4*c4) = h;
            *reinterpret_cast<float4*>(sAlo + r * SWA + 4*c4) = l;
        }
        #pragma unroll
        for (int i = 0; i < 5; i++) {
            int idx = i * 256 + tid;
            int kk = idx / 40;
            int n  = idx % 40;
            float v = bsrc[(size_t)(kbase + kk) * OUTF + n];
            float h = __uint_as_float(tf32_hi(v));
            sBhi[kk * SWB40 + n] = h;
            sBlo[kk * SWB40 + n] = v - h;
        }
        __syncthreads();

        for (int ks = 0; ks < 4; ks++) {
            int kk = ks * 8;
            const float* pa = sAhi + (r0w + qr) * SWA + kk + qc;
            unsigned a0 = FB(pa[0]), a1 = FB(pa[8*SWA]), a2 = FB(pa[4]), a3 = FB(pa[8*SWA+4]);
            const float* pl = sAlo + (r0w + qr) * SWA + kk + qc;
            unsigned l0 = FB(pl[0]), l1 = FB(pl[8*SWA]), l2 = FB(pl[4]), l3 = FB(pl[8*SWA+4]);
            #pragma unroll
            for (int nt = 0; nt < 5; nt++) {
                int col = nt*8 + qr;
                const float* pb = sBhi + (kk + qc) * SWB40 + col;
                unsigned bh0 = FB(pb[0]), bh1 = FB(pb[4*SWB40]);
                const float* pq = sBlo + (kk + qc) * SWB40 + col;
                unsigned bl0 = FB(pq[0]), bl1 = FB(pq[4*SWB40]);
                MMA_TF32(acc[nt], a0,a1,a2,a3, bh0,bh1);
                MMA_TF32(acc[nt], a0,a1,a2,a3, bl0,bl1);
                MMA_TF32(acc[nt], l0,l1,l2,l3, bh0,bh1);
            }
        }
        __syncthreads();
    }

    int rowa = row0 + r0w + qr;
    int rowb = rowa + 8;
    #pragma unroll
    for (int nt = 0; nt < 5; nt++) {
        int col = nt*8 + 2*qc;
        float b0 = bias[col], b1 = bias[col+1];
        if (rowa < nrows)
            *reinterpret_cast<float2*>(out + (size_t)rowa * OUTF + col) =
                make_float2(acc[nt][0] + b0, acc[nt][1] + b1);
        if (rowb < nrows)
            *reinterpret_cast<float2*>(out + (size_t)rowb * OUTF + col) =
                make_float2(acc[nt][2] + b0, acc[nt][3] + b1);
    }
}

// ---------------- launch ----------------
extern "C" void kernel_launch(void* const* d_in, const int* in_sizes, int n_in,
                              void* d_out, int out_size) {
    const float* x   = (const float*)d_in[0];
    const int*   ei  = (const int*)d_in[1];
    const float* Wl0 = (const float*)d_in[2];
    const float* Wr0 = (const float*)d_in[3];
    const float* Wl1 = (const float*)d_in[4];
    const float* Wr1 = (const float*)d_in[5];
    const float* Wl2 = (const float*)d_in[6];
    const float* Wr2 = (const float*)d_in[7];
    const float* b2  = (const float*)d_in[8];
    const float* g0  = (const float*)d_in[9];
    const float* be0 = (const float*)d_in[10];
    const float* g1  = (const float*)d_in[11];
    const float* be1 = (const float*)d_in[12];
    float* out = (float*)d_out;

    int E = in_sizes[1] / 2;
    int N = in_sizes[0] / HIDF;

    float *agg, *h0, *h1, *cnt, *sums, *bnp0, *bnp1;
    cudaGetSymbolAddress((void**)&agg,  g_agg);
    cudaGetSymbolAddress((void**)&h0,   g_h0);
    cudaGetSymbolAddress((void**)&h1,   g_h1);
    cudaGetSymbolAddress((void**)&cnt,  g_cnt);
    cudaGetSymbolAddress((void**)&sums, g_sums);
    cudaGetSymbolAddress((void**)&bnp0, g_bnp0);
    cudaGetSymbolAddress((void**)&bnp1, g_bnp1);

    static int smem_set = 0;
    if (!smem_set) {
        cudaFuncSetAttribute(gemm_tc128_kernel,
                             cudaFuncAttributeMaxDynamicSharedMemorySize, TC128_SMEM);
        cudaFuncSetAttribute(gemm_tc40_kernel,
                             cudaFuncAttributeMaxDynamicSharedMemorySize, TC40_SMEM);
        smem_set = 1;
    }

    const int FEAT4 = N * HIDF / 4;
    int quarter = (E + 3) >> 2;
    int scat_blocks = (int)(((long long)quarter * 32 + 255) / 256);
    int tc_blocks   = (N + 127) / 128;
    int zero_blocks = (FEAT4 + 255) / 256;

    zero_small_kernel<<<(N + 255) / 256, 256>>>(cnt, N);
    zero_small_kernel<<<1, 512>>>(sums, 512);
    degree_kernel<<<(E + 255) / 256, 256>>>(ei, cnt, E, N);

    // ---- layer 0 ----
    zero_kernel<<<zero_blocks, 256>>>((float4*)agg, FEAT4);
    scatter_kernel<<<scat_blocks, 256>>>(x, ei, nullptr, agg, E, N);
    gemm_tc128_kernel<<<tc_blocks, 256, TC128_SMEM>>>(agg, cnt, x, nullptr,
                                                      Wl0, Wr0, h0, sums, N);
    bn_finalize_kernel<<<1, 128>>>(sums, g0, be0, bnp0, N);

    // ---- layer 1 ----
    zero_kernel<<<zero_blocks, 256>>>((float4*)agg, FEAT4);
    scatter_kernel<<<scat_blocks, 256>>>(h0, ei, bnp0, agg, E, N);
    gemm_tc128_kernel<<<tc_blocks, 256, TC128_SMEM>>>(agg, cnt, h0, bnp0,
                                                      Wl1, Wr1, h1, sums + 256, N);
    bn_finalize_kernel<<<1, 128>>>(sums + 256, g1, be1, bnp1, N);

    // ---- layer 2 ----
    zero_kernel<<<zero_blocks, 256>>>((float4*)agg, FEAT4);
    scatter_kernel<<<scat_blocks, 256>>>(h1, ei, bnp1, agg, E, N);
    gemm_tc40_kernel<<<tc_blocks, 256, TC40_SMEM>>>(agg, cnt, h1, bnp1,
                                                    Wl2, Wr2, b2, out, N);
}

// round 7
// speedup vs baseline: 2.5562x; 1.4113x over previous
#include <cuda_runtime.h>
#include <cuda_bf16.h>
#include <cstdint>

#define N_NODES 100000
#define E_EDGES 800000
#define HIDF 128
#define OUTF 40
#define BN_EPS 1e-5f

// ---------------- scratch ----------------
__device__ float g_mean[(size_t)N_NODES * HIDF];
__device__ float g_h0 [(size_t)N_NODES * HIDF];
__device__ float g_h1 [(size_t)N_NODES * HIDF];
__device__ int   g_rowptr[N_NODES + 1];
__device__ int   g_cursor[N_NODES];
__device__ int   g_csr[E_EDGES];
__device__ int   g_bsum[1024];
__device__ float g_sums[512];     // [layer][s:128 | q:128]
__device__ float g_bnp0[256];     // scale[128] | shift[128]
__device__ float g_bnp1[256];

// ---------------- small utils ----------------
__global__ void zero_int_kernel(int* __restrict__ p, int n) {
    int i = blockIdx.x * blockDim.x + threadIdx.x;
    if (i < n) p[i] = 0;
}
__global__ void zero_f_kernel(float* __restrict__ p, int n) {
    int i = blockIdx.x * blockDim.x + threadIdx.x;
    if (i < n) p[i] = 0.0f;
}

// ---------------- CSR build ----------------
__global__ void degree_kernel(const int* __restrict__ ei, int* __restrict__ rowptr,
                              int E, int N) {
    int e = blockIdx.x * blockDim.x + threadIdx.x;
    if (e >= E) return;
    int s = ei[e], d = ei[E + e];
    if ((unsigned)s < (unsigned)N && (unsigned)d < (unsigned)N)
        atomicAdd(&rowptr[d + 1], 1);
}

__global__ void scan1_kernel(int* __restrict__ data, int* __restrict__ bsum, int n) {
    __shared__ int sh[1024];
    int gid = blockIdx.x * 1024 + threadIdx.x;
    int v = (gid < n) ? data[gid] : 0;
    sh[threadIdx.x] = v;
    __syncthreads();
    #pragma unroll
    for (int off = 1; off < 1024; off <<= 1) {
        int t = (threadIdx.x >= off) ? sh[threadIdx.x - off] : 0;
        __syncthreads();
        sh[threadIdx.x] += t;
        __syncthreads();
    }
    if (gid < n) data[gid] = sh[threadIdx.x];
    if (threadIdx.x == 1023) bsum[blockIdx.x] = sh[1023];
}

__global__ void scan2_kernel(int* __restrict__ bsum, int nb) {
    __shared__ int sh[1024];
    int v = (threadIdx.x < nb) ? bsum[threadIdx.x] : 0;
    sh[threadIdx.x] = v;
    __syncthreads();
    #pragma unroll
    for (int off = 1; off < 1024; off <<= 1) {
        int t = (threadIdx.x >= off) ? sh[threadIdx.x - off] : 0;
        __syncthreads();
        sh[threadIdx.x] += t;
        __syncthreads();
    }
    if (threadIdx.x < nb) bsum[threadIdx.x] = sh[threadIdx.x];
}

__global__ void scan3_kernel(int* __restrict__ data, const int* __restrict__ bsum,
                             int* __restrict__ cursor, int n, int N) {
    int gid = blockIdx.x * 1024 + threadIdx.x;
    if (gid >= n) return;
    int add = (blockIdx.x > 0) ? bsum[blockIdx.x - 1] : 0;
    int v = data[gid] + add;
    data[gid] = v;
    if (gid < N) cursor[gid] = v - ((gid == 0) ? 0 : 0);   // cursor[i] = rowptr[i]
}

__global__ void fill_kernel(const int* __restrict__ ei, int* __restrict__ cursor,
                            int* __restrict__ csr, int E, int N) {
    int e = blockIdx.x * blockDim.x + threadIdx.x;
    if (e >= E) return;
    int s = ei[e], d = ei[E + e];
    if ((unsigned)s >= (unsigned)N || (unsigned)d >= (unsigned)N) return;
    int pos = atomicAdd(&cursor[d], 1);
    csr[pos] = s;
}

// Note: scan3 writes cursor[i] = rowptr[i+?]. Careful: data[gid] is the INCLUSIVE
// scan of counts placed at [d+1], so data[i] == rowptr[i] (edges with dst < i).
// cursor must start at rowptr[node] -> cursor[gid] = data[gid]. Done above.

// ---------------- gather-mean (+optional fused BN+ReLU on neighbor rows) ----------
__global__ void __launch_bounds__(256)
gather_kernel(const float* __restrict__ feat,
              const int* __restrict__ rowptr,
              const int* __restrict__ csr,
              const float* __restrict__ bnp,
              float* __restrict__ mean, int N) {
    int node = blockIdx.x * 8 + (threadIdx.x >> 5);
    if (node >= N) return;
    int c = (threadIdx.x & 31) << 2;

    float4 sc = make_float4(1.f,1.f,1.f,1.f), sh = make_float4(0.f,0.f,0.f,0.f);
    bool bn = (bnp != nullptr);
    if (bn) {
        sc = *reinterpret_cast<const float4*>(bnp + c);
        sh = *reinterpret_cast<const float4*>(bnp + 128 + c);
    }

    int beg = rowptr[node], end = rowptr[node + 1];
    float4 acc = make_float4(0.f,0.f,0.f,0.f);
    int j = beg;
    for (; j + 4 <= end; j += 4) {
        int i0 = csr[j], i1 = csr[j+1], i2 = csr[j+2], i3 = csr[j+3];
        float4 v0 = *reinterpret_cast<const float4*>(feat + (size_t)i0 * HIDF + c);
        float4 v1 = *reinterpret_cast<const float4*>(feat + (size_t)i1 * HIDF + c);
        float4 v2 = *reinterpret_cast<const float4*>(feat + (size_t)i2 * HIDF + c);
        float4 v3 = *reinterpret_cast<const float4*>(feat + (size_t)i3 * HIDF + c);
        if (bn) {
            v0.x=fmaxf(fmaf(v0.x,sc.x,sh.x),0.f); v0.y=fmaxf(fmaf(v0.y,sc.y,sh.y),0.f);
            v0.z=fmaxf(fmaf(v0.z,sc.z,sh.z),0.f); v0.w=fmaxf(fmaf(v0.w,sc.w,sh.w),0.f);
            v1.x=fmaxf(fmaf(v1.x,sc.x,sh.x),0.f); v1.y=fmaxf(fmaf(v1.y,sc.y,sh.y),0.f);
            v1.z=fmaxf(fmaf(v1.z,sc.z,sh.z),0.f); v1.w=fmaxf(fmaf(v1.w,sc.w,sh.w),0.f);
            v2.x=fmaxf(fmaf(v2.x,sc.x,sh.x),0.f); v2.y=fmaxf(fmaf(v2.y,sc.y,sh.y),0.f);
            v2.z=fmaxf(fmaf(v2.z,sc.z,sh.z),0.f); v2.w=fmaxf(fmaf(v2.w,sc.w,sh.w),0.f);
            v3.x=fmaxf(fmaf(v3.x,sc.x,sh.x),0.f); v3.y=fmaxf(fmaf(v3.y,sc.y,sh.y),0.f);
            v3.z=fmaxf(fmaf(v3.z,sc.z,sh.z),0.f); v3.w=fmaxf(fmaf(v3.w,sc.w,sh.w),0.f);
        }
        acc.x += v0.x + v1.x + v2.x + v3.x;
        acc.y += v0.y + v1.y + v2.y + v3.y;
        acc.z += v0.z + v1.z + v2.z + v3.z;
        acc.w += v0.w + v1.w + v2.w + v3.w;
    }
    for (; j < end; j++) {
        int i0 = csr[j];
        float4 v0 = *reinterpret_cast<const float4*>(feat + (size_t)i0 * HIDF + c);
        if (bn) {
            v0.x=fmaxf(fmaf(v0.x,sc.x,sh.x),0.f); v0.y=fmaxf(fmaf(v0.y,sc.y,sh.y),0.f);
            v0.z=fmaxf(fmaf(v0.z,sc.z,sh.z),0.f); v0.w=fmaxf(fmaf(v0.w,sc.w,sh.w),0.f);
        }
        acc.x += v0.x; acc.y += v0.y; acc.z += v0.z; acc.w += v0.w;
    }
    float invd = (end > beg) ? 1.0f / (float)(end - beg) : 0.0f;
    acc.x *= invd; acc.y *= invd; acc.z *= invd; acc.w *= invd;
    *reinterpret_cast<float4*>(mean + (size_t)node * HIDF + c) = acc;
}

// ================= bf16 3x-split tensor-core GEMM =================
#define SWH 20     // A smem row stride in bf16x2 words (16 data + 4 pad): conflict-free
#define SWBW 136   // B smem k-word stride (NC=128): 136%32==8 -> conflict-free
#define SWBW40 40  // NC=40: 40%32==8 -> conflict-free

__device__ __forceinline__ unsigned pack_bf16x2(float lo, float hi) {
    unsigned r;
    asm("cvt.rn.bf16x2.f32 %0, %1, %2;" : "=r"(r) : "f"(hi), "f"(lo));
    return r;
}
__device__ __forceinline__ float bf_lo(unsigned u) { return __uint_as_float(u << 16); }
__device__ __forceinline__ float bf_hi(unsigned u) { return __uint_as_float(u & 0xffff0000u); }

#define MMA_BF16(d, A0,A1,A2,A3, B0,B1) \
    asm volatile("mma.sync.aligned.m16n8k16.row.col.f32.bf16.bf16.f32 " \
        "{%0,%1,%2,%3}, {%4,%5,%6,%7}, {%8,%9}, {%0,%1,%2,%3};" \
        : "+f"((d)[0]), "+f"((d)[1]), "+f"((d)[2]), "+f"((d)[3]) \
        : "r"(A0), "r"(A1), "r"(A2), "r"(A3), "r"(B0), "r"(B1))

__device__ __forceinline__ void redg_f32(float* p, float v) {
    asm volatile("red.global.add.f32 [%0], %1;" :: "l"(p), "f"(v) : "memory");
}

// split a float4 (4 consecutive k) into two hi-words and two lo-words
__device__ __forceinline__ void split4(float4 v, unsigned* h, unsigned* l) {
    h[0] = pack_bf16x2(v.x, v.y);
    h[1] = pack_bf16x2(v.z, v.w);
    l[0] = pack_bf16x2(v.x - bf_lo(h[0]), v.y - bf_hi(h[0]));
    l[1] = pack_bf16x2(v.z - bf_lo(h[1]), v.w - bf_hi(h[1]));
}

__global__ void __launch_bounds__(256)
gemm_tc128_kernel(const float* __restrict__ meanm,
                  const float* __restrict__ feat,
                  const float* __restrict__ bnp,   // affine for feat (null = raw)
                  const float* __restrict__ Wl,
                  const float* __restrict__ Wr,
                  float* __restrict__ out,
                  float* __restrict__ stats,
                  int nrows) {
    __shared__ unsigned sAhi[128 * SWH];
    __shared__ unsigned sAlo[128 * SWH];
    __shared__ unsigned sBhi[16 * SWBW];
    __shared__ unsigned sBlo[16 * SWBW];
    __shared__ float    sBn[256];

    int tid  = threadIdx.x;
    int row0 = blockIdx.x * 128;
    int lane = tid & 31;
    int wid  = tid >> 5;
    int qr = lane >> 2, qc = lane & 3;
    int r0w = (wid & 3) * 32;
    int n0w = (wid >> 2) * 64;
    bool hasbn = (bnp != nullptr);

    if (hasbn && tid < 256) sBn[tid] = bnp[tid];
    __syncthreads();

    float acc[2][8][4];
    #pragma unroll
    for (int m = 0; m < 2; m++)
        #pragma unroll
        for (int n = 0; n < 8; n++)
            #pragma unroll
            for (int i = 0; i < 4; i++) acc[m][n][i] = 0.0f;

    for (int chunk = 0; chunk < 8; chunk++) {
        const float* asrc = (chunk < 4) ? meanm : feat;
        const float* bsrc = (chunk < 4) ? Wl : Wr;
        bool applybn = (chunk >= 4) && hasbn;
        int kbase = (chunk & 3) * 32;

        // stage A: 128 rows x 32 k (1024 float4 tasks, 4/thread)
        #pragma unroll
        for (int i = 0; i < 4; i++) {
            int t = i * 256 + tid;
            int r  = t >> 3;
            int c4 = t & 7;
            int row = row0 + r;
            float4 v = make_float4(0.f,0.f,0.f,0.f);
            if (row < nrows) {
                v = *reinterpret_cast<const float4*>(asrc + (size_t)row * HIDF + kbase + 4*c4);
                if (applybn) {
                    int cc = kbase + 4*c4;
                    v.x = fmaxf(fmaf(v.x, sBn[cc+0], sBn[128+cc+0]), 0.f);
                    v.y = fmaxf(fmaf(v.y, sBn[cc+1], sBn[128+cc+1]), 0.f);
                    v.z = fmaxf(fmaf(v.z, sBn[cc+2], sBn[128+cc+2]), 0.f);
                    v.w = fmaxf(fmaf(v.w, sBn[cc+3], sBn[128+cc+3]), 0.f);
                }
            }
            unsigned h[2], l[2];
            split4(v, h, l);
            *reinterpret_cast<uint2*>(sAhi + r * SWH + c4 * 2) = make_uint2(h[0], h[1]);
            *reinterpret_cast<uint2*>(sAlo + r * SWH + c4 * 2) = make_uint2(l[0], l[1]);
        }
        // stage B: 16 kwords x 128 n (512 tasks of 4 cols, 2/thread)
        #pragma unroll
        for (int i = 0; i < 2; i++) {
            int t = i * 256 + tid;
            int kw = t >> 5;
            int n4 = t & 31;
            const float* p0 = bsrc + (size_t)(kbase + 2*kw) * 128 + 4*n4;
            float4 a = *reinterpret_cast<const float4*>(p0);
            float4 b = *reinterpret_cast<const float4*>(p0 + 128);
            unsigned h0 = pack_bf16x2(a.x, b.x), h1 = pack_bf16x2(a.y, b.y);
            unsigned h2 = pack_bf16x2(a.z, b.z), h3 = pack_bf16x2(a.w, b.w);
            unsigned l0 = pack_bf16x2(a.x - bf_lo(h0), b.x - bf_hi(h0));
            unsigned l1 = pack_bf16x2(a.y - bf_lo(h1), b.y - bf_hi(h1));
            unsigned l2 = pack_bf16x2(a.z - bf_lo(h2), b.z - bf_hi(h2));
            unsigned l3 = pack_bf16x2(a.w - bf_lo(h3), b.w - bf_hi(h3));
            *reinterpret_cast<uint4*>(sBhi + kw * SWBW + 4*n4) = make_uint4(h0,h1,h2,h3);
            *reinterpret_cast<uint4*>(sBlo + kw * SWBW + 4*n4) = make_uint4(l0,l1,l2,l3);
        }
        __syncthreads();

        #pragma unroll
        for (int s = 0; s < 2; s++) {
            int wb = s * 8;
            unsigned ah[2][4], al[2][4];
            #pragma unroll
            for (int mt = 0; mt < 2; mt++) {
                int base = (r0w + mt*16 + qr) * SWH + wb + qc;
                ah[mt][0] = sAhi[base];          ah[mt][1] = sAhi[base + 8*SWH];
                ah[mt][2] = sAhi[base + 4];      ah[mt][3] = sAhi[base + 8*SWH + 4];
                al[mt][0] = sAlo[base];          al[mt][1] = sAlo[base + 8*SWH];
                al[mt][2] = sAlo[base + 4];      al[mt][3] = sAlo[base + 8*SWH + 4];
            }
            #pragma unroll
            for (int nt = 0; nt < 8; nt++) {
                int col = n0w + nt*8 + qr;
                unsigned bh0 = sBhi[(wb + qc) * SWBW + col];
                unsigned bh1 = sBhi[(wb + qc + 4) * SWBW + col];
                unsigned bl0 = sBlo[(wb + qc) * SWBW + col];
                unsigned bl1 = sBlo[(wb + qc + 4) * SWBW + col];
                #pragma unroll
                for (int mt = 0; mt < 2; mt++) {
                    MMA_BF16(acc[mt][nt], ah[mt][0],ah[mt][1],ah[mt][2],ah[mt][3], bh0,bh1);
                    MMA_BF16(acc[mt][nt], ah[mt][0],ah[mt][1],ah[mt][2],ah[mt][3], bl0,bl1);
                    MMA_BF16(acc[mt][nt], al[mt][0],al[mt][1],al[mt][2],al[mt][3], bh0,bh1);
                }
            }
        }
        __syncthreads();
    }

    // write out
    #pragma unroll
    for (int mt = 0; mt < 2; mt++) {
        int rowa = row0 + r0w + mt*16 + qr;
        int rowb = rowa + 8;
        #pragma unroll
        for (int nt = 0; nt < 8; nt++) {
            int col = n0w + nt*8 + 2*qc;
            if (rowa < nrows)
                *reinterpret_cast<float2*>(out + (size_t)rowa * HIDF + col) =
                    make_float2(acc[mt][nt][0], acc[mt][nt][1]);
            if (rowb < nrows)
                *reinterpret_cast<float2*>(out + (size_t)rowb * HIDF + col) =
                    make_float2(acc[mt][nt][2], acc[mt][nt][3]);
        }
    }

    // fused BN statistics
    #pragma unroll
    for (int nt = 0; nt < 8; nt++) {
        #pragma unroll
        for (int p = 0; p < 2; p++) {
            float v0 = acc[0][nt][p],   v1 = acc[0][nt][p+2];
            float v2 = acc[1][nt][p],   v3 = acc[1][nt][p+2];
            float s = v0 + v1 + v2 + v3;
            float q = v0*v0 + v1*v1 + v2*v2 + v3*v3;
            #pragma unroll
            for (int off = 4; off < 32; off <<= 1) {
                s += __shfl_xor_sync(0xffffffff, s, off);
                q += __shfl_xor_sync(0xffffffff, q, off);
            }
            if (qr == 0) {
                int col = n0w + nt*8 + 2*qc + p;
                redg_f32(stats + col, s);
                redg_f32(stats + 128 + col, q);
            }
        }
    }
}

// ---- bn finalize ----
__global__ void bn_finalize_kernel(const float* __restrict__ stats,
                                   const float* __restrict__ g,
                                   const float* __restrict__ be,
                                   float* __restrict__ bnp, int nrows) {
    int c = threadIdx.x;
    float invN = 1.0f / (float)nrows;
    float mu  = stats[c] * invN;
    float var = stats[128 + c] * invN - mu * mu;
    float sc  = g[c] * rsqrtf(var + BN_EPS);
    bnp[c]       = sc;
    bnp[128 + c] = be[c] - mu * sc;
}

// ---- NC=40 bf16 variant: 8 warps x 16 rows, 5 n-tiles, + bias ----
__global__ void __launch_bounds__(256)
gemm_tc40_kernel(const float* __restrict__ meanm,
                 const float* __restrict__ feat,
                 const float* __restrict__ bnp,
                 const float* __restrict__ Wl,
                 const float* __restrict__ Wr,
                 const float* __restrict__ bias,
                 float* __restrict__ out, int nrows) {
    __shared__ unsigned sAhi[128 * SWH];
    __shared__ unsigned sAlo[128 * SWH];
    __shared__ unsigned sBhi[16 * SWBW40];
    __shared__ unsigned sBlo[16 * SWBW40];
    __shared__ float    sBn[256];

    int tid  = threadIdx.x;
    int row0 = blockIdx.x * 128;
    int lane = tid & 31;
    int wid  = tid >> 5;
    int qr = lane >> 2, qc = lane & 3;
    int r0w = wid * 16;

    if (tid < 256) sBn[tid] = bnp[tid];
    __syncthreads();

    float acc[5][4];
    #pragma unroll
    for (int n = 0; n < 5; n++)
        #pragma unroll
        for (int i = 0; i < 4; i++) acc[n][i] = 0.0f;

    for (int chunk = 0; chunk < 8; chunk++) {
        const float* asrc = (chunk < 4) ? meanm : feat;
        const float* bsrc = (chunk < 4) ? Wl : Wr;
        bool applybn = (chunk >= 4);
        int kbase = (chunk & 3) * 32;

        #pragma unroll
        for (int i = 0; i < 4; i++) {
            int t = i * 256 + tid;
            int r  = t >> 3;
            int c4 = t & 7;
            int row = row0 + r;
            float4 v = make_float4(0.f,0.f,0.f,0.f);
            if (row < nrows) {
                v = *reinterpret_cast<const float4*>(asrc + (size_t)row * HIDF + kbase + 4*c4);
                if (applybn) {
                    int cc = kbase + 4*c4;
                    v.x = fmaxf(fmaf(v.x, sBn[cc+0], sBn[128+cc+0]), 0.f);
                    v.y = fmaxf(fmaf(v.y, sBn[cc+1], sBn[128+cc+1]), 0.f);
                    v.z = fmaxf(fmaf(v.z, sBn[cc+2], sBn[128+cc+2]), 0.f);
                    v.w = fmaxf(fmaf(v.w, sBn[cc+3], sBn[128+cc+3]), 0.f);
                }
            }
            unsigned h[2], l[2];
            split4(v, h, l);
            *reinterpret_cast<uint2*>(sAhi + r * SWH + c4 * 2) = make_uint2(h[0], h[1]);
            *reinterpret_cast<uint2*>(sAlo + r * SWH + c4 * 2) = make_uint2(l[0], l[1]);
        }
        // stage B: 16 kwords x 40 n (160 tasks of 4 cols)
        if (tid < 160) {
            int kw = tid / 10;
            int n4 = tid % 10;
            const float* p0 = bsrc + (size_t)(kbase + 2*kw) * OUTF + 4*n4;
            float4 a = *reinterpret_cast<const float4*>(p0);
            float4 b = *reinterpret_cast<const float4*>(p0 + OUTF);
            unsigned h0 = pack_bf16x2(a.x, b.x), h1 = pack_bf16x2(a.y, b.y);
            unsigned h2 = pack_bf16x2(a.z, b.z), h3 = pack_bf16x2(a.w, b.w);
            unsigned l0 = pack_bf16x2(a.x - bf_lo(h0), b.x - bf_hi(h0));
            unsigned l1 = pack_bf16x2(a.y - bf_lo(h1), b.y - bf_hi(h1));
            unsigned l2 = pack_bf16x2(a.z - bf_lo(h2), b.z - bf_hi(h2));
            unsigned l3 = pack_bf16x2(a.w - bf_lo(h3), b.w - bf_hi(h3));
            *reinterpret_cast<uint4*>(sBhi + kw * SWBW40 + 4*n4) = make_uint4(h0,h1,h2,h3);
            *reinterpret_cast<uint4*>(sBlo + kw * SWBW40 + 4*n4) = make_uint4(l0,l1,l2,l3);
        }
        __syncthreads();

        #pragma unroll
        for (int s = 0; s < 2; s++) {
            int wb = s * 8;
            int base = (r0w + qr) * SWH + wb + qc;
            unsigned a0 = sAhi[base],     a1 = sAhi[base + 8*SWH];
            unsigned a2 = sAhi[base + 4], a3 = sAhi[base + 8*SWH + 4];
            unsigned l0 = sAlo[base],     l1 = sAlo[base + 8*SWH];
            unsigned l2 = sAlo[base + 4], l3 = sAlo[base + 8*SWH + 4];
            #pragma unroll
            for (int nt = 0; nt < 5; nt++) {
                int col = nt*8 + qr;
                unsigned bh0 = sBhi[(wb + qc) * SWBW40 + col];
                unsigned bh1 = sBhi[(wb + qc + 4) * SWBW40 + col];
                unsigned bl0 = sBlo[(wb + qc) * SWBW40 + col];
                unsigned bl1 = sBlo[(wb + qc + 4) * SWBW40 + col];
                MMA_BF16(acc[nt], a0,a1,a2,a3, bh0,bh1);
                MMA_BF16(acc[nt], a0,a1,a2,a3, bl0,bl1);
                MMA_BF16(acc[nt], l0,l1,l2,l3, bh0,bh1);
            }
        }
        __syncthreads();
    }

    int rowa = row0 + r0w + qr;
    int rowb = rowa + 8;
    #pragma unroll
    for (int nt = 0; nt < 5; nt++) {
        int col = nt*8 + 2*qc;
        float b0 = bias[col], b1 = bias[col+1];
        if (rowa < nrows)
            *reinterpret_cast<float2*>(out + (size_t)rowa * OUTF + col) =
                make_float2(acc[nt][0] + b0, acc[nt][1] + b1);
        if (rowb < nrows)
            *reinterpret_cast<float2*>(out + (size_t)rowb * OUTF + col) =
                make_float2(acc[nt][2] + b0, acc[nt][3] + b1);
    }
}

// ---------------- launch ----------------
extern "C" void kernel_launch(void* const* d_in, const int* in_sizes, int n_in,
                              void* d_out, int out_size) {
    const float* x   = (const float*)d_in[0];
    const int*   ei  = (const int*)d_in[1];
    const float* Wl0 = (const float*)d_in[2];
    const float* Wr0 = (const float*)d_in[3];
    const float* Wl1 = (const float*)d_in[4];
    const float* Wr1 = (const float*)d_in[5];
    const float* Wl2 = (const float*)d_in[6];
    const float* Wr2 = (const float*)d_in[7];
    const float* b2  = (const float*)d_in[8];
    const float* g0  = (const float*)d_in[9];
    const float* be0 = (const float*)d_in[10];
    const float* g1  = (const float*)d_in[11];
    const float* be1 = (const float*)d_in[12];
    float* out = (float*)d_out;

    int E = in_sizes[1] / 2;
    int N = in_sizes[0] / HIDF;

    float *meanm, *h0, *h1, *sums, *bnp0, *bnp1;
    int *rowptr, *cursor, *csr, *bsum;
    cudaGetSymbolAddress((void**)&meanm, g_mean);
    cudaGetSymbolAddress((void**)&h0,    g_h0);
    cudaGetSymbolAddress((void**)&h1,    g_h1);
    cudaGetSymbolAddress((void**)&sums,  g_sums);
    cudaGetSymbolAddress((void**)&bnp0,  g_bnp0);
    cudaGetSymbolAddress((void**)&bnp1,  g_bnp1);
    cudaGetSymbolAddress((void**)&rowptr, g_rowptr);
    cudaGetSymbolAddress((void**)&cursor, g_cursor);
    cudaGetSymbolAddress((void**)&csr,    g_csr);
    cudaGetSymbolAddress((void**)&bsum,   g_bsum);

    int np1 = N + 1;
    int nscan = (np1 + 1023) / 1024;
    int tc_blocks = (N + 127) / 128;
    int ga_blocks = (N + 7) / 8;

    // ---- CSR build (graph static across the 3 layers) ----
    zero_int_kernel<<<(np1 + 255) / 256, 256>>>(rowptr, np1);
    degree_kernel<<<(E + 255) / 256, 256>>>(ei, rowptr, E, N);
    scan1_kernel<<<nscan, 1024>>>(rowptr, bsum, np1);
    scan2_kernel<<<1, 1024>>>(bsum, nscan);
    scan3_kernel<<<nscan, 1024>>>(rowptr, bsum, cursor, np1, N);
    fill_kernel<<<(E + 255) / 256, 256>>>(ei, cursor, csr, E, N);
    zero_f_kernel<<<1, 512>>>(sums, 512);

    // ---- layer 0 ----
    gather_kernel<<<ga_blocks, 256>>>(x, rowptr, csr, nullptr, meanm, N);
    gemm_tc128_kernel<<<tc_blocks, 256>>>(meanm, x, nullptr, Wl0, Wr0, h0, sums, N);
    bn_finalize_kernel<<<1, 128>>>(sums, g0, be0, bnp0, N);

    // ---- layer 1 ----
    gather_kernel<<<ga_blocks, 256>>>(h0, rowptr, csr, bnp0, meanm, N);
    gemm_tc128_kernel<<<tc_blocks, 256>>>(meanm, h0, bnp0, Wl1, Wr1, h1, sums + 256, N);
    bn_finalize_kernel<<<1, 128>>>(sums + 256, g1, be1, bnp1, N);

    // ---- layer 2 ----
    gather_kernel<<<ga_blocks, 256>>>(h1, rowptr, csr, bnp1, meanm, N);
    gemm_tc40_kernel<<<tc_blocks, 256>>>(meanm, h1, bnp1, Wl2, Wr2, b2, out, N);
}